// round 15
// baseline (speedup 1.0000x reference)
#include <cuda_runtime.h>
#include <cuda_fp16.h>
#include <cstdint>

// Model_62886911148434 — seed-guided cluster loss.
// A: gather + mean-pool (round-8 best shape) + evict_last cache hint
// B: mma.sync fp16 GEMM with FP16 ACCUMULATORS (acc 32 regs), 2-stage
//    cp.async pipeline, 3 CTAs/SM (24 warps) via launch_bounds(256,3)
// C: warp-per-sentence softmax/loss + fused deterministic reduction

#define B_ 2048
#define S_ 2048
#define L_ 64
#define LS_ 8
#define D_ 300
#define DP2 320          // padded K (zeros in 300..319): 5 chunks of 64 halfs
#define C_ 64
#define NCHUNK 5
#define LOSS_BLOCKS 256
#define GEMM_SMEM (64 * 1024)   // 2 stages x (A 16KB + B 16KB)

__device__ __half g_snt[2][B_ * DP2];
__device__ __half g_sd [2][S_ * DP2];
__device__ float g_pmax[2][B_ * C_];
__device__ float g_lossb[B_];
__device__ unsigned int g_cnt;   // zero-initialized; reset by last block

__device__ __forceinline__ uint32_t smem_u32(const void* p) {
    uint32_t a;
    asm("{ .reg .u64 t; cvta.to.shared.u64 t, %1; cvt.u32.u64 %0, t; }"
        : "=r"(a) : "l"(p));
    return a;
}

// L2 evict-last access policy on the embedding-table gathers.
__device__ __forceinline__ uint64_t mk_policy() {
    uint64_t pol;
    asm("createpolicy.fractional.L2::evict_last.b64 %0, 1.0;" : "=l"(pol));
    return pol;
}
__device__ __forceinline__ float4 ldg_el(const float* p, uint64_t pol) {
    float4 v;
    asm("ld.global.nc.L2::cache_hint.v4.f32 {%0,%1,%2,%3}, [%4], %5;"
        : "=f"(v.x), "=f"(v.y), "=f"(v.z), "=f"(v.w) : "l"(p), "l"(pol));
    return v;
}

#define CP_ASYNC16(dst, src) \
    asm volatile("cp.async.cg.shared.global [%0], [%1], 16;" \
                 :: "r"(dst), "l"(src) : "memory")
#define CP_COMMIT()  asm volatile("cp.async.commit_group;" ::: "memory")
#define CP_WAIT1()   asm volatile("cp.async.wait_group 1;" ::: "memory")

// ---------------- Stage A: embeddings (fp32 accumulate -> fp16 store) --------
__global__ void __launch_bounds__(96) emb_kernel(
    const int* __restrict__ sents, const int* __restrict__ seeds,
    const float* __restrict__ mask,
    const float* __restrict__ embT, const float* __restrict__ embS)
{
    __shared__ int   s_tok[L_];
    __shared__ float s_msk[L_];

    const int row = blockIdx.x;
    const int f = threadIdx.x;
    const bool act = (f < 75);
    const uint64_t pol = mk_policy();
    float4 at = make_float4(0.f, 0.f, 0.f, 0.f);
    float4 as = make_float4(0.f, 0.f, 0.f, 0.f);

    float sc;
    __half* d0;
    __half* d1;

    if (row < B_) {
        if (f < L_) {
            s_tok[f] = sents[row * L_ + f];
            s_msk[f] = mask [row * L_ + f];
        }
        __syncthreads();

        #pragma unroll 8
        for (int l = 0; l < L_; l++) {
            const int tok = s_tok[l];
            const float m = s_msk[l];
            if (act) {
                const float4 vt = ldg_el(embT + (size_t)tok * D_ + f * 4, pol);
                const float4 vs = ldg_el(embS + (size_t)tok * D_ + f * 4, pol);
                at.x += vt.x * m; at.y += vt.y * m; at.z += vt.z * m; at.w += vt.w * m;
                as.x += vs.x * m; as.y += vs.y * m; as.z += vs.z * m; as.w += vs.w * m;
            }
        }
        float msum = 0.f;
        #pragma unroll
        for (int l = 0; l < L_; l++) msum += s_msk[l];
        sc = 1.f / fmaxf(msum, 1.f);
        d0 = &g_snt[0][row * DP2];
        d1 = &g_snt[1][row * DP2];
    } else {
        const int s = row - B_;
        if (f < LS_) s_tok[f] = seeds[s * LS_ + f];
        __syncthreads();

        #pragma unroll
        for (int l = 0; l < LS_; l++) {
            const int tok = s_tok[l];
            if (act) {
                const float4 vt = ldg_el(embT + (size_t)tok * D_ + f * 4, pol);
                const float4 vs = ldg_el(embS + (size_t)tok * D_ + f * 4, pol);
                at.x += vt.x; at.y += vt.y; at.z += vt.z; at.w += vt.w;
                as.x += vs.x; as.y += vs.y; as.z += vs.z; as.w += vs.w;
            }
        }
        sc = 1.f / (float)LS_;
        d0 = &g_sd[0][s * DP2];
        d1 = &g_sd[1][s * DP2];
    }

    if (act) {
        ((__half2*)(d0 + f * 4))[0] = __floats2half2_rn(at.x * sc, at.y * sc);
        ((__half2*)(d0 + f * 4))[1] = __floats2half2_rn(at.z * sc, at.w * sc);
        ((__half2*)(d1 + f * 4))[0] = __floats2half2_rn(as.x * sc, as.y * sc);
        ((__half2*)(d1 + f * 4))[1] = __floats2half2_rn(as.z * sc, as.w * sc);
    } else if (f < 80) {
        const __half2 z = __floats2half2_rn(0.f, 0.f);
        ((__half2*)(d0 + f * 4))[0] = z;
        ((__half2*)(d0 + f * 4))[1] = z;
        ((__half2*)(d1 + f * 4))[0] = z;
        ((__half2*)(d1 + f * 4))[1] = z;
    }
}

// ---------------- Stage B: fp16-acc mma.sync GEMM + per-cluster max ----------
// Block: 256 threads (8 warps, 2x4), tile 128(m) x 128(n), warp tile 64x32.
// fp16 accumulators halve acc regs (32/thread) -> 3 CTAs/SM with the 85-reg
// cap from launch_bounds(256,3). 2-stage cp.async pipeline (64KB smem).
__global__ void __launch_bounds__(256, 3) gemm_max_kernel()
{
    extern __shared__ __align__(16) uint4 smem_dyn[];

    const int tid = threadIdx.x;
    const int wid = tid >> 5, lane = tid & 31;
    const int warp_m = wid >> 2, warp_n = wid & 3;
    const int z = blockIdx.z, bcol = blockIdx.x, brow = blockIdx.y;

    const __half* Ag = &g_snt[z][(size_t)brow * 128 * DP2];
    const __half* Bg = &g_sd [z][(size_t)bcol * 128 * DP2];

    const uint32_t aBase = smem_u32(smem_dyn);
    const uint32_t bBase = aBase + 16384u;
    uint32_t dstA[4], dstB[4];
    const __half* srcA[4];
    const __half* srcB[4];
    #pragma unroll
    for (int it = 0; it < 4; it++) {
        const int i = it * 256 + tid;
        const int rr = i >> 3, cc = i & 7;
        const uint32_t sw = (uint32_t)(rr * 128 + ((cc ^ (rr & 7)) << 4));
        dstA[it] = aBase + sw;
        dstB[it] = bBase + sw;
        srcA[it] = Ag + (size_t)rr * DP2 + cc * 8;
        srcB[it] = Bg + (size_t)rr * DP2 + cc * 8;
    }

    uint32_t preA[4]; int a7[4];
    #pragma unroll
    for (int mf = 0; mf < 4; mf++) {
        const int rA = warp_m * 64 + mf * 16 + (lane & 7) + ((lane >> 3) & 1) * 8;
        preA[mf] = aBase + rA * 128;
        a7[mf] = rA & 7;
    }
    const int cA = lane >> 4;
    uint32_t preB[2]; int b7[2];
    #pragma unroll
    for (int g = 0; g < 2; g++) {
        const int rB = warp_n * 32 + g * 16 + (lane & 7) + (lane >> 4) * 8;
        preB[g] = bBase + rB * 128;
        b7[g] = rB & 7;
    }
    const int cB = (lane >> 3) & 1;

    // fp16 accumulators: [mf][nf][2] b32 regs (each = half2)
    uint32_t acc[4][4][2];
    #pragma unroll
    for (int mf = 0; mf < 4; mf++)
        #pragma unroll
        for (int nf = 0; nf < 4; nf++) {
            acc[mf][nf][0] = 0u;
            acc[mf][nf][1] = 0u;
        }

    // prologue: stage0 <- chunk0, stage1 <- chunk1
    #pragma unroll
    for (int it = 0; it < 4; it++) {
        CP_ASYNC16(dstA[it], srcA[it]);
        CP_ASYNC16(dstB[it], srcB[it]);
    }
    CP_COMMIT();
    #pragma unroll
    for (int it = 0; it < 4; it++) {
        CP_ASYNC16(dstA[it] + 32768u, srcA[it] + 64);
        CP_ASYNC16(dstB[it] + 32768u, srcB[it] + 64);
    }
    CP_COMMIT();

    for (int ch = 0; ch < NCHUNK; ch++) {
        CP_WAIT1();                   // chunk ch landed (ch+1 may be in flight)
        __syncthreads();

        const uint32_t stOff = (uint32_t)(ch & 1) * 32768u;
        #pragma unroll
        for (int s = 0; s < 4; s++) {
            uint32_t af[4][4];
            #pragma unroll
            for (int mf = 0; mf < 4; mf++) {
                const uint32_t addr = preA[mf] + stOff + ((uint32_t)(((2 * s + cA) ^ a7[mf]) << 4));
                asm volatile("ldmatrix.sync.aligned.m8n8.x4.shared.b16 {%0,%1,%2,%3}, [%4];"
                    : "=r"(af[mf][0]), "=r"(af[mf][1]), "=r"(af[mf][2]), "=r"(af[mf][3])
                    : "r"(addr));
            }
            uint32_t bf[2][4];
            #pragma unroll
            for (int g = 0; g < 2; g++) {
                const uint32_t addr = preB[g] + stOff + ((uint32_t)(((2 * s + cB) ^ b7[g]) << 4));
                asm volatile("ldmatrix.sync.aligned.m8n8.x4.shared.b16 {%0,%1,%2,%3}, [%4];"
                    : "=r"(bf[g][0]), "=r"(bf[g][1]), "=r"(bf[g][2]), "=r"(bf[g][3])
                    : "r"(addr));
            }
            #pragma unroll
            for (int mf = 0; mf < 4; mf++)
                #pragma unroll
                for (int nf = 0; nf < 4; nf++) {
                    const uint32_t b0 = bf[nf >> 1][(nf & 1) * 2 + 0];
                    const uint32_t b1 = bf[nf >> 1][(nf & 1) * 2 + 1];
                    asm volatile(
                        "mma.sync.aligned.m16n8k16.row.col.f16.f16.f16.f16 "
                        "{%0,%1}, {%2,%3,%4,%5}, {%6,%7}, {%0,%1};"
                        : "+r"(acc[mf][nf][0]), "+r"(acc[mf][nf][1])
                        : "r"(af[mf][0]), "r"(af[mf][1]), "r"(af[mf][2]), "r"(af[mf][3]),
                          "r"(b0), "r"(b1));
                }
        }

        __syncthreads();              // all warps done reading stage ch&1
        if (ch + 2 < NCHUNK) {
            const uint32_t so = (uint32_t)(ch & 1) * 32768u;
            const int kc = (ch + 2) * 64;
            #pragma unroll
            for (int it = 0; it < 4; it++) {
                CP_ASYNC16(dstA[it] + so, srcA[it] + kc);
                CP_ASYNC16(dstB[it] + so, srcB[it] + kc);
            }
        }
        CP_COMMIT();                  // constant group count (empty ok)
    }

    // Epilogue: reg0 = (row r, cols 2c,2c+1), reg1 = (row r+8, same cols),
    // r = warp_m*64+mf*16+(lane>>2), c = lane&3 within the nf 8-col group.
    const int cluster = bcol * 4 + warp_n;
    #pragma unroll
    for (int mf = 0; mf < 4; mf++) {
        float mlo = -3.402823466e38f, mhi = -3.402823466e38f;
        #pragma unroll
        for (int nf = 0; nf < 4; nf++) {
            const float2 lo = __half22float2(*(const __half2*)&acc[mf][nf][0]);
            const float2 hi = __half22float2(*(const __half2*)&acc[mf][nf][1]);
            mlo = fmaxf(mlo, fmaxf(lo.x, lo.y));
            mhi = fmaxf(mhi, fmaxf(hi.x, hi.y));
        }
        mlo = fmaxf(mlo, __shfl_xor_sync(0xffffffffu, mlo, 1));
        mlo = fmaxf(mlo, __shfl_xor_sync(0xffffffffu, mlo, 2));
        mhi = fmaxf(mhi, __shfl_xor_sync(0xffffffffu, mhi, 1));
        mhi = fmaxf(mhi, __shfl_xor_sync(0xffffffffu, mhi, 2));
        if ((lane & 3) == 0) {
            const int grow = brow * 128 + warp_m * 64 + mf * 16 + (lane >> 2);
            g_pmax[z][grow * C_ + cluster] = mlo;
            g_pmax[z][(grow + 8) * C_ + cluster] = mhi;
        }
    }
}

// ---------------- Stage C: warp-per-sentence loss + fused reduction ----------
__global__ void __launch_bounds__(256) loss_kernel(float* __restrict__ out)
{
    const int tid = threadIdx.x;
    const int lane = tid & 31, w = tid >> 5;
    const int b = blockIdx.x * 8 + w;

    const float t0 = g_pmax[0][b * C_ + lane];
    const float t1 = g_pmax[0][b * C_ + 32 + lane];
    const float s0 = g_pmax[1][b * C_ + lane];
    const float s1 = g_pmax[1][b * C_ + 32 + lane];

    float m = fmaxf(t0, t1);
    #pragma unroll
    for (int o = 16; o > 0; o >>= 1)
        m = fmaxf(m, __shfl_xor_sync(0xffffffffu, m, o));

    const float e0 = expf(t0 - m);
    const float e1 = expf(t1 - m);
    float Z = e0 + e1;
    #pragma unroll
    for (int o = 16; o > 0; o >>= 1)
        Z += __shfl_xor_sync(0xffffffffu, Z, o);

    const float inv_Z = 1.f / Z;
    const float reli = inv_Z - (1.f / (float)C_);   // max prob = exp(0)/Z
    const float wgt = 1.f + 0.5f * fabsf(reli);
    const float d0 = e0 * inv_Z - s0;
    const float d1 = e1 * inv_Z - s1;
    float q = d0 * d0 + d1 * d1;
    #pragma unroll
    for (int o = 16; o > 0; o >>= 1)
        q += __shfl_xor_sync(0xffffffffu, q, o);
    if (lane == 0) g_lossb[b] = wgt * q;

    __shared__ int is_last;
    __shared__ float sh[8];
    __threadfence();
    __syncthreads();
    if (tid == 0) {
        const unsigned int o = atomicAdd(&g_cnt, 1u);
        is_last = (o == (unsigned int)(LOSS_BLOCKS - 1));
    }
    __syncthreads();
    if (is_last) {
        __threadfence();
        float sum = 0.f;
        for (int i = tid; i < B_; i += 256) sum += g_lossb[i];
        #pragma unroll
        for (int o = 16; o > 0; o >>= 1)
            sum += __shfl_xor_sync(0xffffffffu, sum, o);
        if (lane == 0) sh[w] = sum;
        __syncthreads();
        if (tid == 0) {
            float tot = 0.f;
            #pragma unroll
            for (int i = 0; i < 8; i++) tot += sh[i];
            out[0] = tot * (1.f / (float)B_);
            g_cnt = 0;   // reset for next graph replay
        }
    }
}

extern "C" void kernel_launch(void* const* d_in, const int* in_sizes, int n_in,
                              void* d_out, int out_size)
{
    const int* sents = nullptr;
    const int* seeds = nullptr;
    const float* mask = nullptr;
    const float* embT = nullptr;
    const float* embS = nullptr;
    int c131 = 0, c15m = 0;
    for (int i = 0; i < n_in; i++) {
        const int sz = in_sizes[i];
        if (sz == B_ * L_) {
            if (c131 == 0) sents = (const int*)d_in[i];
            else           mask  = (const float*)d_in[i];
            c131++;
        } else if (sz == S_ * LS_) {
            seeds = (const int*)d_in[i];
        } else if (sz == 50000 * D_) {
            if (c15m == 0) embT = (const float*)d_in[i];
            else           embS = (const float*)d_in[i];
            c15m++;
        }
    }

    cudaFuncSetAttribute(gemm_max_kernel,
                         cudaFuncAttributeMaxDynamicSharedMemorySize, GEMM_SMEM);

    emb_kernel<<<B_ + S_, 96>>>(sents, seeds, mask, embT, embS);
    gemm_max_kernel<<<dim3(16, 16, 2), 256, GEMM_SMEM>>>();
    loss_kernel<<<LOSS_BLOCKS, 256>>>((float*)d_out);
}

// round 16
// speedup vs baseline: 1.0485x; 1.0485x over previous
#include <cuda_runtime.h>
#include <cuda_fp16.h>
#include <cstdint>

// Model_62886911148434 — seed-guided cluster loss.
// A: gather + mean-pool (round-8 best shape) + evict_last cache hint
// B: mma.sync GEMM with fp16 accumulators, 128x128 tiles,
//    3-stage cp.async pipeline (exact R14 structure; only acc dtype changed)
// C: warp-per-sentence softmax/loss + fused deterministic reduction

#define B_ 2048
#define S_ 2048
#define L_ 64
#define LS_ 8
#define D_ 300
#define DP2 320          // padded K (zeros in 300..319): 5 chunks of 64 halfs
#define C_ 64
#define NCHUNK 5
#define LOSS_BLOCKS 256
#define GEMM_SMEM (96 * 1024)   // 3 stages x (A 16KB + B 16KB)

__device__ __half g_snt[2][B_ * DP2];
__device__ __half g_sd [2][S_ * DP2];
__device__ float g_pmax[2][B_ * C_];
__device__ float g_lossb[B_];
__device__ unsigned int g_cnt;   // zero-initialized; reset by last block

__device__ __forceinline__ uint32_t smem_u32(const void* p) {
    uint32_t a;
    asm("{ .reg .u64 t; cvta.to.shared.u64 t, %1; cvt.u32.u64 %0, t; }"
        : "=r"(a) : "l"(p));
    return a;
}

// L2 evict-last access policy on the embedding-table gathers.
__device__ __forceinline__ uint64_t mk_policy() {
    uint64_t pol;
    asm("createpolicy.fractional.L2::evict_last.b64 %0, 1.0;" : "=l"(pol));
    return pol;
}
__device__ __forceinline__ float4 ldg_el(const float* p, uint64_t pol) {
    float4 v;
    asm("ld.global.nc.L2::cache_hint.v4.f32 {%0,%1,%2,%3}, [%4], %5;"
        : "=f"(v.x), "=f"(v.y), "=f"(v.z), "=f"(v.w) : "l"(p), "l"(pol));
    return v;
}

#define CP_ASYNC16(dst, src) \
    asm volatile("cp.async.cg.shared.global [%0], [%1], 16;" \
                 :: "r"(dst), "l"(src) : "memory")
#define CP_COMMIT()  asm volatile("cp.async.commit_group;" ::: "memory")
#define CP_WAIT1()   asm volatile("cp.async.wait_group 1;" ::: "memory")

// ---------------- Stage A: embeddings (fp32 accumulate -> fp16 store) --------
__global__ void __launch_bounds__(96) emb_kernel(
    const int* __restrict__ sents, const int* __restrict__ seeds,
    const float* __restrict__ mask,
    const float* __restrict__ embT, const float* __restrict__ embS)
{
    __shared__ int   s_tok[L_];
    __shared__ float s_msk[L_];

    const int row = blockIdx.x;
    const int f = threadIdx.x;
    const bool act = (f < 75);
    const uint64_t pol = mk_policy();
    float4 at = make_float4(0.f, 0.f, 0.f, 0.f);
    float4 as = make_float4(0.f, 0.f, 0.f, 0.f);

    float sc;
    __half* d0;
    __half* d1;

    if (row < B_) {
        if (f < L_) {
            s_tok[f] = sents[row * L_ + f];
            s_msk[f] = mask [row * L_ + f];
        }
        __syncthreads();

        #pragma unroll 8
        for (int l = 0; l < L_; l++) {
            const int tok = s_tok[l];
            const float m = s_msk[l];
            if (act) {
                const float4 vt = ldg_el(embT + (size_t)tok * D_ + f * 4, pol);
                const float4 vs = ldg_el(embS + (size_t)tok * D_ + f * 4, pol);
                at.x += vt.x * m; at.y += vt.y * m; at.z += vt.z * m; at.w += vt.w * m;
                as.x += vs.x * m; as.y += vs.y * m; as.z += vs.z * m; as.w += vs.w * m;
            }
        }
        float msum = 0.f;
        #pragma unroll
        for (int l = 0; l < L_; l++) msum += s_msk[l];
        sc = 1.f / fmaxf(msum, 1.f);
        d0 = &g_snt[0][row * DP2];
        d1 = &g_snt[1][row * DP2];
    } else {
        const int s = row - B_;
        if (f < LS_) s_tok[f] = seeds[s * LS_ + f];
        __syncthreads();

        #pragma unroll
        for (int l = 0; l < LS_; l++) {
            const int tok = s_tok[l];
            if (act) {
                const float4 vt = ldg_el(embT + (size_t)tok * D_ + f * 4, pol);
                const float4 vs = ldg_el(embS + (size_t)tok * D_ + f * 4, pol);
                at.x += vt.x; at.y += vt.y; at.z += vt.z; at.w += vt.w;
                as.x += vs.x; as.y += vs.y; as.z += vs.z; as.w += vs.w;
            }
        }
        sc = 1.f / (float)LS_;
        d0 = &g_sd[0][s * DP2];
        d1 = &g_sd[1][s * DP2];
    }

    if (act) {
        ((__half2*)(d0 + f * 4))[0] = __floats2half2_rn(at.x * sc, at.y * sc);
        ((__half2*)(d0 + f * 4))[1] = __floats2half2_rn(at.z * sc, at.w * sc);
        ((__half2*)(d1 + f * 4))[0] = __floats2half2_rn(as.x * sc, as.y * sc);
        ((__half2*)(d1 + f * 4))[1] = __floats2half2_rn(as.z * sc, as.w * sc);
    } else if (f < 80) {
        const __half2 z = __floats2half2_rn(0.f, 0.f);
        ((__half2*)(d0 + f * 4))[0] = z;
        ((__half2*)(d0 + f * 4))[1] = z;
        ((__half2*)(d1 + f * 4))[0] = z;
        ((__half2*)(d1 + f * 4))[1] = z;
    }
}

// ---------------- Stage B: fp16-acc mma.sync GEMM + per-cluster max ----------
// Block: 256 threads (8 warps, 2x4), tile 128(m) x 128(n), warp tile 64x32.
// 3-stage cp.async pipeline (R14 structure): wait_group 1 -> sync -> issue
// chunk ch+2 -> compute ch. Only the accumulator dtype differs from R14.
__global__ void __launch_bounds__(256, 2) gemm_max_kernel()
{
    extern __shared__ __align__(16) uint4 smem_dyn[];

    const int tid = threadIdx.x;
    const int wid = tid >> 5, lane = tid & 31;
    const int warp_m = wid >> 2, warp_n = wid & 3;
    const int z = blockIdx.z, bcol = blockIdx.x, brow = blockIdx.y;

    const __half* Ag = &g_snt[z][(size_t)brow * 128 * DP2];
    const __half* Bg = &g_sd [z][(size_t)bcol * 128 * DP2];

    const uint32_t aBase = smem_u32(smem_dyn);
    const uint32_t bBase = aBase + 16384u;
    uint32_t dstA[4], dstB[4];
    const __half* srcA[4];
    const __half* srcB[4];
    #pragma unroll
    for (int it = 0; it < 4; it++) {
        const int i = it * 256 + tid;
        const int rr = i >> 3, cc = i & 7;
        const uint32_t sw = (uint32_t)(rr * 128 + ((cc ^ (rr & 7)) << 4));
        dstA[it] = aBase + sw;
        dstB[it] = bBase + sw;
        srcA[it] = Ag + (size_t)rr * DP2 + cc * 8;
        srcB[it] = Bg + (size_t)rr * DP2 + cc * 8;
    }

    uint32_t preA[4]; int a7[4];
    #pragma unroll
    for (int mf = 0; mf < 4; mf++) {
        const int rA = warp_m * 64 + mf * 16 + (lane & 7) + ((lane >> 3) & 1) * 8;
        preA[mf] = aBase + rA * 128;
        a7[mf] = rA & 7;
    }
    const int cA = lane >> 4;
    uint32_t preB[2]; int b7[2];
    #pragma unroll
    for (int g = 0; g < 2; g++) {
        const int rB = warp_n * 32 + g * 16 + (lane & 7) + (lane >> 4) * 8;
        preB[g] = bBase + rB * 128;
        b7[g] = rB & 7;
    }
    const int cB = (lane >> 3) & 1;

    // fp16 accumulators: [mf][nf][2] b32 regs (each = half2)
    uint32_t acc[4][4][2];
    #pragma unroll
    for (int mf = 0; mf < 4; mf++)
        #pragma unroll
        for (int nf = 0; nf < 4; nf++) {
            acc[mf][nf][0] = 0u;
            acc[mf][nf][1] = 0u;
        }

    // prologue: stage 0 <- chunk 0, stage 1 <- chunk 1
    #pragma unroll
    for (int it = 0; it < 4; it++) {
        CP_ASYNC16(dstA[it], srcA[it]);
        CP_ASYNC16(dstB[it], srcB[it]);
    }
    CP_COMMIT();
    #pragma unroll
    for (int it = 0; it < 4; it++) {
        CP_ASYNC16(dstA[it] + 32768u, srcA[it] + 64);
        CP_ASYNC16(dstB[it] + 32768u, srcB[it] + 64);
    }
    CP_COMMIT();

    int stage = 0;                    // stage of chunk ch
    for (int ch = 0; ch < NCHUNK; ch++) {
        CP_WAIT1();                   // chunk ch's group complete
        __syncthreads();              // stage (ch+2)%3 free for refill

        if (ch + 2 < NCHUNK) {
            const int nst = (stage + 2 >= 3) ? stage - 1 : stage + 2;
            const uint32_t so = (uint32_t)nst * 32768u;
            const int kc = (ch + 2) * 64;
            #pragma unroll
            for (int it = 0; it < 4; it++) {
                CP_ASYNC16(dstA[it] + so, srcA[it] + kc);
                CP_ASYNC16(dstB[it] + so, srcB[it] + kc);
            }
        }
        CP_COMMIT();                  // constant group count (empty ok)

        const uint32_t stOff = (uint32_t)stage * 32768u;
        #pragma unroll
        for (int s = 0; s < 4; s++) {
            uint32_t af[4][4];
            #pragma unroll
            for (int mf = 0; mf < 4; mf++) {
                const uint32_t addr = preA[mf] + stOff + ((uint32_t)(((2 * s + cA) ^ a7[mf]) << 4));
                asm volatile("ldmatrix.sync.aligned.m8n8.x4.shared.b16 {%0,%1,%2,%3}, [%4];"
                    : "=r"(af[mf][0]), "=r"(af[mf][1]), "=r"(af[mf][2]), "=r"(af[mf][3])
                    : "r"(addr));
            }
            uint32_t bf[2][4];
            #pragma unroll
            for (int g = 0; g < 2; g++) {
                const uint32_t addr = preB[g] + stOff + ((uint32_t)(((2 * s + cB) ^ b7[g]) << 4));
                asm volatile("ldmatrix.sync.aligned.m8n8.x4.shared.b16 {%0,%1,%2,%3}, [%4];"
                    : "=r"(bf[g][0]), "=r"(bf[g][1]), "=r"(bf[g][2]), "=r"(bf[g][3])
                    : "r"(addr));
            }
            #pragma unroll
            for (int mf = 0; mf < 4; mf++)
                #pragma unroll
                for (int nf = 0; nf < 4; nf++) {
                    const uint32_t b0 = bf[nf >> 1][(nf & 1) * 2 + 0];
                    const uint32_t b1 = bf[nf >> 1][(nf & 1) * 2 + 1];
                    asm volatile(
                        "mma.sync.aligned.m16n8k16.row.col.f16.f16.f16.f16 "
                        "{%0,%1}, {%2,%3,%4,%5}, {%6,%7}, {%0,%1};"
                        : "+r"(acc[mf][nf][0]), "+r"(acc[mf][nf][1])
                        : "r"(af[mf][0]), "r"(af[mf][1]), "r"(af[mf][2]), "r"(af[mf][3]),
                          "r"(b0), "r"(b1));
                }
        }

        stage = (stage + 1 >= 3) ? 0 : stage + 1;
    }

    // Epilogue: reg0 = (row r, col pair), reg1 = (row r+8, same cols);
    // r = warp_m*64 + mf*16 + (lane>>2). Reduce lane&3 group via shfl.
    const int cluster = bcol * 4 + warp_n;
    #pragma unroll
    for (int mf = 0; mf < 4; mf++) {
        float mlo = -3.402823466e38f, mhi = -3.402823466e38f;
        #pragma unroll
        for (int nf = 0; nf < 4; nf++) {
            const float2 lo = __half22float2(*(const __half2*)&acc[mf][nf][0]);
            const float2 hi = __half22float2(*(const __half2*)&acc[mf][nf][1]);
            mlo = fmaxf(mlo, fmaxf(lo.x, lo.y));
            mhi = fmaxf(mhi, fmaxf(hi.x, hi.y));
        }
        mlo = fmaxf(mlo, __shfl_xor_sync(0xffffffffu, mlo, 1));
        mlo = fmaxf(mlo, __shfl_xor_sync(0xffffffffu, mlo, 2));
        mhi = fmaxf(mhi, __shfl_xor_sync(0xffffffffu, mhi, 1));
        mhi = fmaxf(mhi, __shfl_xor_sync(0xffffffffu, mhi, 2));
        if ((lane & 3) == 0) {
            const int grow = brow * 128 + warp_m * 64 + mf * 16 + (lane >> 2);
            g_pmax[z][grow * C_ + cluster] = mlo;
            g_pmax[z][(grow + 8) * C_ + cluster] = mhi;
        }
    }
}

// ---------------- Stage C: warp-per-sentence loss + fused reduction ----------
__global__ void __launch_bounds__(256) loss_kernel(float* __restrict__ out)
{
    const int tid = threadIdx.x;
    const int lane = tid & 31, w = tid >> 5;
    const int b = blockIdx.x * 8 + w;

    const float t0 = g_pmax[0][b * C_ + lane];
    const float t1 = g_pmax[0][b * C_ + 32 + lane];
    const float s0 = g_pmax[1][b * C_ + lane];
    const float s1 = g_pmax[1][b * C_ + 32 + lane];

    float m = fmaxf(t0, t1);
    #pragma unroll
    for (int o = 16; o > 0; o >>= 1)
        m = fmaxf(m, __shfl_xor_sync(0xffffffffu, m, o));

    const float e0 = expf(t0 - m);
    const float e1 = expf(t1 - m);
    float Z = e0 + e1;
    #pragma unroll
    for (int o = 16; o > 0; o >>= 1)
        Z += __shfl_xor_sync(0xffffffffu, Z, o);

    const float inv_Z = 1.f / Z;
    const float reli = inv_Z - (1.f / (float)C_);   // max prob = exp(0)/Z
    const float wgt = 1.f + 0.5f * fabsf(reli);
    const float d0 = e0 * inv_Z - s0;
    const float d1 = e1 * inv_Z - s1;
    float q = d0 * d0 + d1 * d1;
    #pragma unroll
    for (int o = 16; o > 0; o >>= 1)
        q += __shfl_xor_sync(0xffffffffu, q, o);
    if (lane == 0) g_lossb[b] = wgt * q;

    __shared__ int is_last;
    __shared__ float sh[8];
    __threadfence();
    __syncthreads();
    if (tid == 0) {
        const unsigned int o = atomicAdd(&g_cnt, 1u);
        is_last = (o == (unsigned int)(LOSS_BLOCKS - 1));
    }
    __syncthreads();
    if (is_last) {
        __threadfence();
        float sum = 0.f;
        for (int i = tid; i < B_; i += 256) sum += g_lossb[i];
        #pragma unroll
        for (int o = 16; o > 0; o >>= 1)
            sum += __shfl_xor_sync(0xffffffffu, sum, o);
        if (lane == 0) sh[w] = sum;
        __syncthreads();
        if (tid == 0) {
            float tot = 0.f;
            #pragma unroll
            for (int i = 0; i < 8; i++) tot += sh[i];
            out[0] = tot * (1.f / (float)B_);
            g_cnt = 0;   // reset for next graph replay
        }
    }
}

extern "C" void kernel_launch(void* const* d_in, const int* in_sizes, int n_in,
                              void* d_out, int out_size)
{
    const int* sents = nullptr;
    const int* seeds = nullptr;
    const float* mask = nullptr;
    const float* embT = nullptr;
    const float* embS = nullptr;
    int c131 = 0, c15m = 0;
    for (int i = 0; i < n_in; i++) {
        const int sz = in_sizes[i];
        if (sz == B_ * L_) {
            if (c131 == 0) sents = (const int*)d_in[i];
            else           mask  = (const float*)d_in[i];
            c131++;
        } else if (sz == S_ * LS_) {
            seeds = (const int*)d_in[i];
        } else if (sz == 50000 * D_) {
            if (c15m == 0) embT = (const float*)d_in[i];
            else           embS = (const float*)d_in[i];
            c15m++;
        }
    }

    cudaFuncSetAttribute(gemm_max_kernel,
                         cudaFuncAttributeMaxDynamicSharedMemorySize, GEMM_SMEM);

    emb_kernel<<<B_ + S_, 96>>>(sents, seeds, mask, embT, embS);
    gemm_max_kernel<<<dim3(16, 16, 2), 256, GEMM_SMEM>>>();
    loss_kernel<<<LOSS_BLOCKS, 256>>>((float*)d_out);
}